// round 2
// baseline (speedup 1.0000x reference)
#include <cuda_runtime.h>
#include <math.h>

// ---------------- problem constants ----------------
#define NB    8      // batch
#define BCAP  32     // B_ input capsules
#define NC    32     // C_ output capsules
#define WIN   14
#define WOUT  6
#define WW    36     // WOUT*WOUT
#define BKK   288    // K*K*B_
#define CWW   1152   // C_*WOUT*WOUT
#define EPSV  1e-10f
#define HALF_LN2PI 0.91893853320467274178f

// ---------------- device scratch (static: allocation-free) ----------------
__device__ float g_ap[(size_t)NB * CWW * BKK];           // R numerators, layout [b][cww][i]
__device__ float g_part[NB * 32 * BKK];                  // partial denom sums
__device__ float g_denom[NB * BKK];                      // denom[b][i]

__device__ __forceinline__ float4 rowmul(float4 wr, float4 p0, float4 p1, float4 p2, float4 p3) {
    float4 r;
    r.x = wr.x*p0.x + wr.y*p1.x + wr.z*p2.x + wr.w*p3.x;
    r.y = wr.x*p0.y + wr.y*p1.y + wr.z*p2.y + wr.w*p3.y;
    r.z = wr.x*p0.z + wr.y*p1.z + wr.z*p2.z + wr.w*p3.z;
    r.w = wr.x*p0.w + wr.y*p1.w + wr.z*p2.w + wr.w*p3.w;
    return r;
}

// One block per output column (b, cww). 288 threads = 16 h-lanes x 18 g-groups.
// Every phase RECOMPUTES votes from poses/W (both L2-resident: 3.2MB + 0.6MB),
// so no 162MB votes tensor ever touches DRAM.
// Thread t computes the 4x4 vote for input capsule i=t, stores it to smem,
// then re-reads in (g,h) layout: thread (g,h) owns V[i=g+18k, h], k=0..15.
// PHASE 0: R = 1/C implicit, write ap.
// PHASE 1: R from ap/denom, write ap (column-local, in-place safe).
// PHASE 2: R from ap/denom, write mu + a to d_out.
template <int PHASE>
__global__ __launch_bounds__(BKK, 4)
void em_kernel(const float* __restrict__ poses, const float* __restrict__ act,
               const float* __restrict__ Wt, const float* __restrict__ beta_v,
               const float* __restrict__ beta_a, const float* __restrict__ lam,
               float* __restrict__ out)
{
    const int cww = blockIdx.x;
    const int b   = blockIdx.y;
    const int c   = cww / WW;
    const int s   = cww - c * WW;
    const int yw  = s / WOUT;
    const int xw  = s - yw * WOUT;
    const int t   = threadIdx.x;
    const int g   = t >> 4;        // 0..17
    const int h   = t & 15;        // 0..15
    const size_t colbase = (size_t)(b * CWW + cww) * BKK;

    __shared__ __align__(16) float Vs[BKK * 16];   // 18KB vote transpose buffer
    __shared__ float Rw[BKK];
    __shared__ float red[BKK];
    __shared__ float red2[18];
    __shared__ float mu_s[16], logsig_s[16], inv2s_s[16];
    __shared__ float sumR_s, a_s;

    float Vr[16];

    // ---- compute votes: thread t == input-capsule index i; V_i = W_i @ P_i (4x4) ----
    const int i  = t;
    const int Bc = i / 9, uv = i - Bc * 9, u = uv / 3, v = uv - u * 3;
    {
        const float4* Pp = reinterpret_cast<const float4*>(
            poses + ((size_t)((b * BCAP + Bc) * WIN + (2 * xw + u)) * WIN + (2 * yw + v)) * 16);
        const float4* Wp = reinterpret_cast<const float4*>(
            Wt + (size_t)(((Bc * 3 + u) * 3 + v) * NC + c) * 16);
        float4 p0 = Pp[0], p1 = Pp[1], p2 = Pp[2], p3 = Pp[3];
        float4 w0 = Wp[0], w1 = Wp[1], w2 = Wp[2], w3 = Wp[3];
        float4* vsl = reinterpret_cast<float4*>(Vs + i * 16);
        vsl[0] = rowmul(w0, p0, p1, p2, p3);
        vsl[1] = rowmul(w1, p0, p1, p2, p3);
        vsl[2] = rowmul(w2, p0, p1, p2, p3);
        vsl[3] = rowmul(w3, p0, p1, p2, p3);
    }

    // ---- Rw[i] = R[i] * a_[i] (overlap the act/ap/denom loads with the smem fill) ----
    {
        const float av = act[((b * BCAP + Bc) * WIN + (2 * xw + u)) * WIN + (2 * yw + v)];
        float R;
        if (PHASE == 0) R = 1.0f / 32.0f;
        else            R = g_ap[colbase + i] / (g_denom[b * BKK + i] + EPSV) + EPSV;
        Rw[i] = R * av;
    }
    __syncthreads();

    #pragma unroll
    for (int k = 0; k < 16; k++) Vr[k] = Vs[(g + 18 * k) * 16 + h];

    // ---- mu numerators + sum_R ----
    float accm = 0.f, accr = 0.f;
    #pragma unroll
    for (int k = 0; k < 16; k++) {
        const float rw = Rw[g + 18 * k];
        accm = fmaf(rw, Vr[k], accm);
        accr += rw;
    }
    red[g * 16 + h] = accm;
    if (h == 0) red2[g] = accr;
    __syncthreads();
    float rsum = 0.f;
    if (t < 16) {
        #pragma unroll
        for (int j = 0; j < 18; j++) rsum += red[j * 16 + t];
    }
    if (t == 0) {
        float sr = 0.f;
        #pragma unroll
        for (int j = 0; j < 18; j++) sr += red2[j];
        sumR_s = sr;
    }
    __syncthreads();
    if (t < 16) mu_s[t] = rsum / sumR_s;
    __syncthreads();
    const float mu_h = mu_s[h];

    // ---- sigma^2 ----
    float accs = 0.f;
    #pragma unroll
    for (int k = 0; k < 16; k++) {
        const float d = Vr[k] - mu_h;
        accs = fmaf(Rw[g + 18 * k], d * d, accs);
    }
    red[g * 16 + h] = accs;
    __syncthreads();
    if (t < 16) {
        float ss = 0.f;
        #pragma unroll
        for (int j = 0; j < 18; j++) ss += red[j * 16 + t];
        const float sig = ss / sumR_s;
        logsig_s[t] = __logf(sqrtf(sig) + EPSV);
        inv2s_s[t]  = 0.5f / sig;
    }
    __syncthreads();

    // ---- activation a = sigmoid(lambda * (beta_a - cost)) ----
    if (t == 0) {
        float lsum = 0.f;
        #pragma unroll
        for (int j = 0; j < 16; j++) lsum += logsig_s[j];
        const float cost = sumR_s * (16.f * beta_v[c] + lsum);
        const float z = lam[0] * (beta_a[c] - cost);
        a_s = 1.f / (1.f + __expf(-z));
    }
    __syncthreads();

    if (PHASE == 2) {
        // outputs: mu [b][cww][16] then a [b][cww]
        if (t < 16) out[(size_t)(b * CWW + cww) * 16 + t] = mu_s[t];
        if (t == 0) out[(size_t)NB * CWW * 16 + b * CWW + cww] = a_s;
        return;
    }

    // ---- p-pass: ap[i] = a * sum_h exp(ln_p) ----
    const float inv2s = inv2s_s[h];
    const float lc    = logsig_s[h] + HALF_LN2PI;
    const float an    = a_s;
    #pragma unroll
    for (int k = 0; k < 16; k++) {
        const float d = Vr[k] - mu_h;
        float p = __expf(fmaf(-(d * d), inv2s, -lc));
        // sum across the 16 h-lanes (xor masks < 16 stay inside each half-warp group)
        p += __shfl_xor_sync(0xffffffffu, p, 1);
        p += __shfl_xor_sync(0xffffffffu, p, 2);
        p += __shfl_xor_sync(0xffffffffu, p, 4);
        p += __shfl_xor_sync(0xffffffffu, p, 8);
        if (h == 0) g_ap[colbase + g + 18 * k] = an * p;
    }
}

// denom[b][i] = sum over cww of ap[b][cww][i] — deterministic two-stage reduction
__global__ __launch_bounds__(BKK)
void denom_part_kernel()
{
    const int chunk = blockIdx.x;   // 0..31, 36 cww rows each
    const int b     = blockIdx.y;
    const int i     = threadIdx.x;
    const float* ap = g_ap + (size_t)(b * CWW + chunk * 36) * BKK + i;
    float sv = 0.f;
    #pragma unroll 4
    for (int j = 0; j < 36; j++) sv += ap[(size_t)j * BKK];
    g_part[(b * 32 + chunk) * BKK + i] = sv;
}

__global__ __launch_bounds__(BKK)
void denom_final_kernel()
{
    const int b = blockIdx.x;
    const int i = threadIdx.x;
    float sv = 0.f;
    #pragma unroll
    for (int j = 0; j < 32; j++) sv += g_part[(b * 32 + j) * BKK + i];
    g_denom[b * BKK + i] = sv;
}

extern "C" void kernel_launch(void* const* d_in, const int* in_sizes, int n_in,
                              void* d_out, int out_size)
{
    (void)in_sizes; (void)n_in; (void)out_size;
    const float* poses = (const float*)d_in[0];
    const float* act   = (const float*)d_in[1];
    const float* Wt    = (const float*)d_in[2];
    const float* bv    = (const float*)d_in[3];
    const float* ba    = (const float*)d_in[4];
    const float* lam   = (const float*)d_in[5];
    float* out = (float*)d_out;

    dim3 grid(CWW, NB);
    em_kernel<0><<<grid, BKK>>>(poses, act, Wt, bv, ba, lam, out);
    denom_part_kernel<<<dim3(32, NB), BKK>>>();
    denom_final_kernel<<<NB, BKK>>>();
    em_kernel<1><<<grid, BKK>>>(poses, act, Wt, bv, ba, lam, out);
    denom_part_kernel<<<dim3(32, NB), BKK>>>();
    denom_final_kernel<<<NB, BKK>>>();
    em_kernel<2><<<grid, BKK>>>(poses, act, Wt, bv, ba, lam, out);
}

// round 3
// speedup vs baseline: 1.5503x; 1.5503x over previous
#include <cuda_runtime.h>
#include <cuda_fp16.h>
#include <math.h>

// ---------------- problem constants ----------------
#define NB    8      // batch
#define BCAP  32     // B_ input capsules
#define NC    32     // C_ output capsules
#define WIN   14
#define WOUT  6
#define WW    36     // WOUT*WOUT
#define BKK   288    // K*K*B_
#define CWW   1152   // C_*WOUT*WOUT
#define EPSV  1e-10f
#define HALF_LN2PI 0.91893853320467274178f

// ---------------- device scratch (static: allocation-free) ----------------
__device__ __half g_votes_h[(size_t)NB * CWW * BKK * 16];  // 81 MB fp16 votes [b][cww][i][h]
__device__ float  g_ap[(size_t)NB * CWW * BKK];            // R numerators [b][cww][i]
__device__ float  g_part[NB * 32 * BKK];                   // partial denom sums
__device__ float  g_denom[NB * BKK];                       // denom[b][i]

__device__ __forceinline__ float4 rowmul(float4 wr, float4 p0, float4 p1, float4 p2, float4 p3) {
    float4 r;
    r.x = wr.x*p0.x + wr.y*p1.x + wr.z*p2.x + wr.w*p3.x;
    r.y = wr.x*p0.y + wr.y*p1.y + wr.z*p2.y + wr.w*p3.y;
    r.z = wr.x*p0.z + wr.y*p1.z + wr.z*p2.z + wr.w*p3.z;
    r.w = wr.x*p0.w + wr.y*p1.w + wr.z*p2.w + wr.w*p3.w;
    return r;
}

__device__ __forceinline__ unsigned int h2u(__half2 x) {
    return *reinterpret_cast<unsigned int*>(&x);
}

// One block per output column (b, cww). 288 threads = 16 h-lanes x 18 g-groups.
// Thread (g,h) owns V[i, h] for i = g + 18k, k=0..15 -> fp16 global offset t + 288k (coalesced).
// PHASE 0: compute votes (fp32 in smem, fp16 to DRAM), EM iter 0 (R = 1/C), write ap.
// PHASE 1: read fp16 votes, R from ap/denom, EM iter, write ap.
// PHASE 2: read fp16 votes, R from ap/denom, final EM iter, write mu + a to d_out.
template <int PHASE>
__global__ __launch_bounds__(BKK)
void em_kernel(const float* __restrict__ poses, const float* __restrict__ act,
               const float* __restrict__ Wt, const float* __restrict__ beta_v,
               const float* __restrict__ beta_a, const float* __restrict__ lam,
               float* __restrict__ out)
{
    const int cww = blockIdx.x;
    const int b   = blockIdx.y;
    const int c   = cww / WW;
    const int s   = cww - c * WW;
    const int yw  = s / WOUT;
    const int xw  = s - yw * WOUT;
    const int t   = threadIdx.x;
    const int g   = t >> 4;        // 0..17
    const int h   = t & 15;        // 0..15
    const size_t colbase = (size_t)(b * CWW + cww) * BKK;

    __shared__ float Rw[BKK];
    __shared__ float red[BKK];          // reused: mu/sigma partials (144), p staging (288)
    __shared__ float red2[18];
    __shared__ float mu_s[16], logsig_s[16], inv2s_s[16];
    __shared__ float sumR_s, a_s;

    float Vr[16];

    const int i  = t;
    const int Bc = i / 9, uv = i - Bc * 9, u = uv / 3, v = uv - u * 3;
    const float av = act[((b * BCAP + Bc) * WIN + (2 * xw + u)) * WIN + (2 * yw + v)];

    if (PHASE == 0) {
        // 20-float padded rows: STS.128 conflict-free, transpose LDS near-conflict-free
        __shared__ __align__(16) float Vs[BKK * 20];
        const float4* Pp = reinterpret_cast<const float4*>(
            poses + ((size_t)((b * BCAP + Bc) * WIN + (2 * xw + u)) * WIN + (2 * yw + v)) * 16);
        const float4* Wp = reinterpret_cast<const float4*>(
            Wt + (size_t)(((Bc * 3 + u) * 3 + v) * NC + c) * 16);
        float4 p0 = Pp[0], p1 = Pp[1], p2 = Pp[2], p3 = Pp[3];
        float4 w0 = Wp[0], w1 = Wp[1], w2 = Wp[2], w3 = Wp[3];
        float4 r0 = rowmul(w0, p0, p1, p2, p3);
        float4 r1 = rowmul(w1, p0, p1, p2, p3);
        float4 r2 = rowmul(w2, p0, p1, p2, p3);
        float4 r3 = rowmul(w3, p0, p1, p2, p3);
        float4* vsl = reinterpret_cast<float4*>(Vs + i * 20);
        vsl[0] = r0; vsl[1] = r1; vsl[2] = r2; vsl[3] = r3;
        // pack to fp16 and store (2x STG.128, fully coalesced)
        uint4 u0 = make_uint4(h2u(__floats2half2_rn(r0.x, r0.y)), h2u(__floats2half2_rn(r0.z, r0.w)),
                              h2u(__floats2half2_rn(r1.x, r1.y)), h2u(__floats2half2_rn(r1.z, r1.w)));
        uint4 u1 = make_uint4(h2u(__floats2half2_rn(r2.x, r2.y)), h2u(__floats2half2_rn(r2.z, r2.w)),
                              h2u(__floats2half2_rn(r3.x, r3.y)), h2u(__floats2half2_rn(r3.z, r3.w)));
        uint4* vg = reinterpret_cast<uint4*>(g_votes_h + colbase * 16 + (size_t)i * 16);
        vg[0] = u0; vg[1] = u1;

        Rw[i] = (1.0f / 32.0f) * av;
        __syncthreads();
        #pragma unroll
        for (int k = 0; k < 16; k++) Vr[k] = Vs[(g + 18 * k) * 20 + h];
    } else {
        const __half* vp = g_votes_h + colbase * 16;
        #pragma unroll
        for (int k = 0; k < 16; k++) Vr[k] = __half2float(vp[t + 288 * k]);
        const float R = g_ap[colbase + i] / (g_denom[b * BKK + i] + EPSV) + EPSV;
        Rw[i] = R * av;
        __syncthreads();
    }

    // ---- mu numerators + sum_R ----
    float accm = 0.f, accr = 0.f;
    #pragma unroll
    for (int k = 0; k < 16; k++) {
        const float rw = Rw[g + 18 * k];
        accm = fmaf(rw, Vr[k], accm);
        accr += rw;
    }
    accm += __shfl_xor_sync(0xffffffffu, accm, 16);   // combine the 2 g-groups in each warp
    if ((t & 31) < 16) red[(t >> 5) * 16 + h] = accm; // 9 warps x 16 h
    if (h == 0) red2[g] = accr;
    __syncthreads();
    if (t < 16) {
        float rsum = 0.f;
        #pragma unroll
        for (int w = 0; w < 9; w++) rsum += red[w * 16 + t];
        float sr = 0.f;
        #pragma unroll
        for (int j = 0; j < 18; j++) sr += red2[j];
        if (t == 0) sumR_s = sr;
        mu_s[t] = rsum / sr;
    }
    __syncthreads();
    const float mu_h = mu_s[h];

    // ---- sigma^2 ----
    float accs = 0.f;
    #pragma unroll
    for (int k = 0; k < 16; k++) {
        const float d = Vr[k] - mu_h;
        accs = fmaf(Rw[g + 18 * k], d * d, accs);
    }
    accs += __shfl_xor_sync(0xffffffffu, accs, 16);
    if ((t & 31) < 16) red[(t >> 5) * 16 + h] = accs;
    __syncthreads();
    if (t < 16) {
        float ss = 0.f;
        #pragma unroll
        for (int w = 0; w < 9; w++) ss += red[w * 16 + t];
        const float sig = ss / sumR_s;
        const float ls  = __logf(sqrtf(sig) + EPSV);
        logsig_s[t] = ls;
        inv2s_s[t]  = 0.5f / sig;
        // activation via in-warp reduce over the 16 active lanes (all in warp 0)
        float lsum = ls;
        lsum += __shfl_xor_sync(0x0000ffffu, lsum, 1);
        lsum += __shfl_xor_sync(0x0000ffffu, lsum, 2);
        lsum += __shfl_xor_sync(0x0000ffffu, lsum, 4);
        lsum += __shfl_xor_sync(0x0000ffffu, lsum, 8);
        if (t == 0) {
            const float cost = sumR_s * (16.f * beta_v[c] + lsum);
            const float z = lam[0] * (beta_a[c] - cost);
            a_s = 1.f / (1.f + __expf(-z));
        }
    }
    __syncthreads();

    if (PHASE == 2) {
        // outputs: mu [b][cww][16] then a [b][cww]
        if (t < 16) out[(size_t)(b * CWW + cww) * 16 + t] = mu_s[t];
        if (t == 0) out[(size_t)NB * CWW * 16 + b * CWW + cww] = a_s;
        return;
    }

    // ---- p-pass: ap[i] = a * sum_h exp(ln_p); stage in smem for coalesced store ----
    const float inv2s = inv2s_s[h];
    const float lc    = logsig_s[h] + HALF_LN2PI;
    #pragma unroll
    for (int k = 0; k < 16; k++) {
        const float d = Vr[k] - mu_h;
        float p = __expf(fmaf(-(d * d), inv2s, -lc));
        p += __shfl_xor_sync(0xffffffffu, p, 1);
        p += __shfl_xor_sync(0xffffffffu, p, 2);
        p += __shfl_xor_sync(0xffffffffu, p, 4);
        p += __shfl_xor_sync(0xffffffffu, p, 8);
        if (h == 0) red[g + 18 * k] = p;
    }
    __syncthreads();
    g_ap[colbase + t] = a_s * red[t];   // one fully-coalesced 1152B store per block
}

// denom[b][i] = sum over cww of ap[b][cww][i] — deterministic two-stage reduction
__global__ __launch_bounds__(BKK)
void denom_part_kernel()
{
    const int chunk = blockIdx.x;   // 0..31, 36 cww rows each
    const int b     = blockIdx.y;
    const int i     = threadIdx.x;
    const float* ap = g_ap + (size_t)(b * CWW + chunk * 36) * BKK + i;
    float sv = 0.f;
    #pragma unroll 4
    for (int j = 0; j < 36; j++) sv += ap[(size_t)j * BKK];
    g_part[(b * 32 + chunk) * BKK + i] = sv;
}

__global__ __launch_bounds__(BKK)
void denom_final_kernel()
{
    const int b = blockIdx.x;
    const int i = threadIdx.x;
    float sv = 0.f;
    #pragma unroll
    for (int j = 0; j < 32; j++) sv += g_part[(b * 32 + j) * BKK + i];
    g_denom[b * BKK + i] = sv;
}

extern "C" void kernel_launch(void* const* d_in, const int* in_sizes, int n_in,
                              void* d_out, int out_size)
{
    (void)in_sizes; (void)n_in; (void)out_size;
    const float* poses = (const float*)d_in[0];
    const float* act   = (const float*)d_in[1];
    const float* Wt    = (const float*)d_in[2];
    const float* bv    = (const float*)d_in[3];
    const float* ba    = (const float*)d_in[4];
    const float* lam   = (const float*)d_in[5];
    float* out = (float*)d_out;

    dim3 grid(CWW, NB);
    em_kernel<0><<<grid, BKK>>>(poses, act, Wt, bv, ba, lam, out);
    denom_part_kernel<<<dim3(32, NB), BKK>>>();
    denom_final_kernel<<<NB, BKK>>>();
    em_kernel<1><<<grid, BKK>>>(poses, act, Wt, bv, ba, lam, out);
    denom_part_kernel<<<dim3(32, NB), BKK>>>();
    denom_final_kernel<<<NB, BKK>>>();
    em_kernel<2><<<grid, BKK>>>(poses, act, Wt, bv, ba, lam, out);
}

// round 4
// speedup vs baseline: 1.8628x; 1.2016x over previous
#include <cuda_runtime.h>
#include <cuda_fp16.h>
#include <math.h>

// ---------------- problem constants ----------------
#define NB    8      // batch
#define BCAP  32     // B_ input capsules
#define NC    32     // C_ output capsules
#define WIN   14
#define WOUT  6
#define WW    36     // WOUT*WOUT
#define BKK   288    // K*K*B_
#define CWW   1152   // C_*WOUT*WOUT
#define EPSV  1e-10f
#define HALF_LN2PI 0.91893853320467274178f

// ---------------- device scratch (static: allocation-free) ----------------
__device__ __half g_votes_h[(size_t)NB * CWW * BKK * 16];  // 81 MB fp16 votes [b][x][i][h]
__device__ float  g_ap[(size_t)NB * CWW * BKK];            // R numerators [b][x][i]
__device__ float  g_part[NB * 32 * BKK];                   // partial denom sums
__device__ float  g_denom[NB * BKK];                       // denom[b][i]

__device__ __forceinline__ float4 rowmul(float4 wr, float4 p0, float4 p1, float4 p2, float4 p3) {
    float4 r;
    r.x = wr.x*p0.x + wr.y*p1.x + wr.z*p2.x + wr.w*p3.x;
    r.y = wr.x*p0.y + wr.y*p1.y + wr.z*p2.y + wr.w*p3.y;
    r.z = wr.x*p0.z + wr.y*p1.z + wr.z*p2.z + wr.w*p3.z;
    r.w = wr.x*p0.w + wr.y*p1.w + wr.z*p2.w + wr.w*p3.w;
    return r;
}

__device__ __forceinline__ unsigned int h2u(__half2 x) {
    return *reinterpret_cast<unsigned int*>(&x);
}

// One block per output column. blockIdx.x = x = s*32 + c (consecutive blocks share
// the same poses patch for L2 locality). 288 threads = 36 g-groups x 8 h-pairs (q).
// Thread (g,q) owns V[i = g+36k, h=2q..2q+1] for k=0..7.
//   gmem half2 index (i,q) = i*8 + q -> warp (4 g x 8 q) covers 128 contiguous bytes.
// PHASE 0: compute votes (i=t), store fp16, __syncthreads, then same path as others.
// PHASE 1: R from ap/denom, EM iter, write ap.
// PHASE 2: final EM iter, write mu + a to d_out.
template <int PHASE>
__global__ __launch_bounds__(BKK)
void em_kernel(const float* __restrict__ poses, const float* __restrict__ act,
               const float* __restrict__ Wt, const float* __restrict__ beta_v,
               const float* __restrict__ beta_a, const float* __restrict__ lam,
               float* __restrict__ out)
{
    const int x   = blockIdx.x;
    const int b   = blockIdx.y;
    const int c   = x & 31;
    const int s   = x >> 5;
    const int yw  = s / WOUT;
    const int xw  = s - yw * WOUT;
    const int t   = threadIdx.x;
    const int g   = t >> 3;        // 0..35
    const int q   = t & 7;         // 0..7 (h-pair)
    const int w   = t >> 5;        // warp 0..8
    const int lane = t & 31;
    const size_t colbase = (size_t)(b * CWW + x) * BKK;

    __shared__ float  Rw[BKK];
    __shared__ float2 redm[9][8];        // per-warp vector partials (float[9][16] view)
    __shared__ float  red2[9];
    __shared__ float  red[BKK];          // p staging
    __shared__ float  mu_s[16], logsig_s[16], inv2s_s[16];
    __shared__ float  sumR_s, a_s;

    // ---- Rw fill (thread t <-> capsule i = t) ----
    const int i  = t;
    const int Bc = i / 9, uv = i - Bc * 9, u = uv / 3, v = uv - u * 3;
    const float av = act[((b * BCAP + Bc) * WIN + (2 * xw + u)) * WIN + (2 * yw + v)];

    if (PHASE == 0) {
        // compute the 4x4 vote for capsule i, store fp16 (2x STG.128, coalesced)
        const float4* Pp = reinterpret_cast<const float4*>(
            poses + ((size_t)((b * BCAP + Bc) * WIN + (2 * xw + u)) * WIN + (2 * yw + v)) * 16);
        const float4* Wp = reinterpret_cast<const float4*>(
            Wt + (size_t)(((Bc * 3 + u) * 3 + v) * NC + c) * 16);
        float4 p0 = Pp[0], p1 = Pp[1], p2 = Pp[2], p3 = Pp[3];
        float4 w0 = Wp[0], w1 = Wp[1], w2 = Wp[2], w3 = Wp[3];
        float4 r0 = rowmul(w0, p0, p1, p2, p3);
        float4 r1 = rowmul(w1, p0, p1, p2, p3);
        float4 r2 = rowmul(w2, p0, p1, p2, p3);
        float4 r3 = rowmul(w3, p0, p1, p2, p3);
        uint4 u0 = make_uint4(h2u(__floats2half2_rn(r0.x, r0.y)), h2u(__floats2half2_rn(r0.z, r0.w)),
                              h2u(__floats2half2_rn(r1.x, r1.y)), h2u(__floats2half2_rn(r1.z, r1.w)));
        uint4 u1 = make_uint4(h2u(__floats2half2_rn(r2.x, r2.y)), h2u(__floats2half2_rn(r2.z, r2.w)),
                              h2u(__floats2half2_rn(r3.x, r3.y)), h2u(__floats2half2_rn(r3.z, r3.w)));
        uint4* vg = reinterpret_cast<uint4*>(g_votes_h + colbase * 16 + (size_t)i * 16);
        vg[0] = u0; vg[1] = u1;
        Rw[i] = (1.0f / 32.0f) * av;
    } else {
        const float R = g_ap[colbase + i] / (g_denom[b * BKK + i] + EPSV) + EPSV;
        Rw[i] = R * av;
    }
    __syncthreads();   // Rw visible; (PHASE 0) own votes visible block-wide

    // ---- load votes: 8x LDG.32 half2, perfectly coalesced ----
    float2 Vr[8];
    const __half2* vp = reinterpret_cast<const __half2*>(g_votes_h + colbase * 16) + q;
    #pragma unroll
    for (int k = 0; k < 8; k++) Vr[k] = __half22float2(vp[(g + 36 * k) * 8]);

    // ---- mu numerators + sum_R ----
    float2 accm = make_float2(0.f, 0.f);
    float  accr = 0.f;
    #pragma unroll
    for (int k = 0; k < 8; k++) {
        const float rw = Rw[g + 36 * k];
        accm.x = fmaf(rw, Vr[k].x, accm.x);
        accm.y = fmaf(rw, Vr[k].y, accm.y);
        accr += rw;
    }
    accm.x += __shfl_xor_sync(0xffffffffu, accm.x, 8);
    accm.y += __shfl_xor_sync(0xffffffffu, accm.y, 8);
    accr   += __shfl_xor_sync(0xffffffffu, accr,   8);
    accm.x += __shfl_xor_sync(0xffffffffu, accm.x, 16);
    accm.y += __shfl_xor_sync(0xffffffffu, accm.y, 16);
    accr   += __shfl_xor_sync(0xffffffffu, accr,   16);
    if (lane < 8) { redm[w][lane] = accm; if (lane == 0) red2[w] = accr; }
    __syncthreads();
    if (t < 16) {
        const float* rm = reinterpret_cast<const float*>(redm);
        float rsum = 0.f, sr = 0.f;
        #pragma unroll
        for (int j = 0; j < 9; j++) { rsum += rm[j * 16 + t]; sr += red2[j]; }
        if (t == 0) sumR_s = sr;
        mu_s[t] = rsum / sr;
    }
    __syncthreads();
    const float2 mu2 = make_float2(mu_s[2 * q], mu_s[2 * q + 1]);

    // ---- sigma^2 ----
    float2 accs = make_float2(0.f, 0.f);
    #pragma unroll
    for (int k = 0; k < 8; k++) {
        const float rw = Rw[g + 36 * k];
        const float dx = Vr[k].x - mu2.x;
        const float dy = Vr[k].y - mu2.y;
        accs.x = fmaf(rw * dx, dx, accs.x);
        accs.y = fmaf(rw * dy, dy, accs.y);
    }
    accs.x += __shfl_xor_sync(0xffffffffu, accs.x, 8);
    accs.y += __shfl_xor_sync(0xffffffffu, accs.y, 8);
    accs.x += __shfl_xor_sync(0xffffffffu, accs.x, 16);
    accs.y += __shfl_xor_sync(0xffffffffu, accs.y, 16);
    if (lane < 8) redm[w][lane] = accs;
    __syncthreads();
    if (t < 16) {
        const float* rm = reinterpret_cast<const float*>(redm);
        float ss = 0.f;
        #pragma unroll
        for (int j = 0; j < 9; j++) ss += rm[j * 16 + t];
        const float sig = ss / sumR_s;
        const float ls  = __logf(sqrtf(sig) + EPSV);
        logsig_s[t] = ls;
        inv2s_s[t]  = 0.5f / sig;
        float lsum = ls;
        lsum += __shfl_xor_sync(0x0000ffffu, lsum, 1);
        lsum += __shfl_xor_sync(0x0000ffffu, lsum, 2);
        lsum += __shfl_xor_sync(0x0000ffffu, lsum, 4);
        lsum += __shfl_xor_sync(0x0000ffffu, lsum, 8);
        if (t == 0) {
            const float cost = sumR_s * (16.f * beta_v[c] + lsum);
            const float z = lam[0] * (beta_a[c] - cost);
            a_s = 1.f / (1.f + __expf(-z));
        }
    }
    __syncthreads();

    if (PHASE == 2) {
        const int cww_out = c * WW + s;
        if (t < 16) out[(size_t)(b * CWW + cww_out) * 16 + t] = mu_s[t];
        if (t == 0) out[(size_t)NB * CWW * 16 + b * CWW + cww_out] = a_s;
        return;
    }

    // ---- p-pass: ap[i] = a * sum_h exp(ln_p) ----
    const float2 il = make_float2(inv2s_s[2 * q], inv2s_s[2 * q + 1]);
    const float2 lc = make_float2(logsig_s[2 * q] + HALF_LN2PI, logsig_s[2 * q + 1] + HALF_LN2PI);
    #pragma unroll
    for (int k = 0; k < 8; k++) {
        const float dx = Vr[k].x - mu2.x;
        const float dy = Vr[k].y - mu2.y;
        float p = __expf(fmaf(-dx * dx, il.x, -lc.x)) + __expf(fmaf(-dy * dy, il.y, -lc.y));
        p += __shfl_xor_sync(0xffffffffu, p, 1);
        p += __shfl_xor_sync(0xffffffffu, p, 2);
        p += __shfl_xor_sync(0xffffffffu, p, 4);
        if (q == 0) red[g + 36 * k] = p;
    }
    __syncthreads();
    g_ap[colbase + t] = a_s * red[t];   // one fully-coalesced 1152B store per block
}

// denom[b][i] = sum over x of ap[b][x][i] — deterministic two-stage reduction
__global__ __launch_bounds__(BKK)
void denom_part_kernel()
{
    const int chunk = blockIdx.x;   // 0..31, 36 x-rows each
    const int b     = blockIdx.y;
    const int i     = threadIdx.x;
    const float* ap = g_ap + (size_t)(b * CWW + chunk * 36) * BKK + i;
    float sv = 0.f;
    #pragma unroll 4
    for (int j = 0; j < 36; j++) sv += ap[(size_t)j * BKK];
    g_part[(b * 32 + chunk) * BKK + i] = sv;
}

__global__ __launch_bounds__(BKK)
void denom_final_kernel()
{
    const int b = blockIdx.x;
    const int i = threadIdx.x;
    float sv = 0.f;
    #pragma unroll
    for (int j = 0; j < 32; j++) sv += g_part[(b * 32 + j) * BKK + i];
    g_denom[b * BKK + i] = sv;
}

extern "C" void kernel_launch(void* const* d_in, const int* in_sizes, int n_in,
                              void* d_out, int out_size)
{
    (void)in_sizes; (void)n_in; (void)out_size;
    const float* poses = (const float*)d_in[0];
    const float* act   = (const float*)d_in[1];
    const float* Wt    = (const float*)d_in[2];
    const float* bv    = (const float*)d_in[3];
    const float* ba    = (const float*)d_in[4];
    const float* lam   = (const float*)d_in[5];
    float* out = (float*)d_out;

    dim3 grid(CWW, NB);
    em_kernel<0><<<grid, BKK>>>(poses, act, Wt, bv, ba, lam, out);
    denom_part_kernel<<<dim3(32, NB), BKK>>>();
    denom_final_kernel<<<NB, BKK>>>();
    em_kernel<1><<<grid, BKK>>>(poses, act, Wt, bv, ba, lam, out);
    denom_part_kernel<<<dim3(32, NB), BKK>>>();
    denom_final_kernel<<<NB, BKK>>>();
    em_kernel<2><<<grid, BKK>>>(poses, act, Wt, bv, ba, lam, out);
}